// round 2
// baseline (speedup 1.0000x reference)
#include <cuda_runtime.h>
#include <math.h>

// Problem constants
static constexpr int NB = 8, NC = 256, NH = 128, NW = 128;
static constexpr int HW = NH * NW;
static constexpr float EPSF = 1e-8f;

// Tiling: core tile 16x32, halo 18x36 (half-shifts only need dy>=0 halo)
static constexpr int TH = 16, TW = 32;
static constexpr int HY = TH + 2, HX = TW + 4;   // 18 x 36
static constexpr int NPIX = HY * HX;             // 648
static constexpr int HALF = NPIX / 2;            // 324 (even/odd swizzle split)
static constexpr int CC = 16;                    // channels per staged chunk
static constexpr int NCHUNK = NC / CC;           // 16
static constexpr int NT = 128;                   // threads (each owns a 2x2 pixel quad)

// Scratch (device globals; no allocation allowed)
__device__ float g_total[NB];
__device__ int   g_cnt[NB];
__device__ int   g_inc[NB];

__device__ __forceinline__ float dot4(const float4& a, const float4& b) {
    return fmaf(a.x, b.x, fmaf(a.y, b.y, fmaf(a.z, b.z, a.w * b.w)));
}

// ---------------------------------------------------------------------------
// Kernel 0: zero accumulators (replaces the 21us stats kernel; stats fused).
// ---------------------------------------------------------------------------
__global__ void zero_kernel() {
    int t = threadIdx.x;
    if (t < NB) { g_total[t] = 0.f; g_cnt[t] = 0; g_inc[t] = 0; }
}

// ---------------------------------------------------------------------------
// Kernel 1: main tiled kernel. 128 threads, 2x2 pixels per thread.
// ---------------------------------------------------------------------------
__global__ __launch_bounds__(NT) void context_kernel(
    const float* __restrict__ er,
    const int*   __restrict__ seg,
    const int*   __restrict__ gtb)
{
    __shared__ float4 sh[4 * NPIX];   // 41472 B, even/odd-swizzled per channel-quad
    __shared__ float  shNorm[NPIX];   // 2592 B (raw pixel index)
    __shared__ int    shLab[NPIX];    // 2592 B: seg | valid<<16 | fg<<17
    __shared__ float  shRedF[NT / 32];
    __shared__ int    shRedC[NT / 32];
    __shared__ int    shRedI[NT / 32];

    const int b  = blockIdx.z;
    const int h0 = blockIdx.y * TH;
    const int w0 = blockIdx.x * TW;
    const int tid = threadIdx.x;
    const int qx = tid & 15;          // 0..15 (x quad)
    const int qy = tid >> 4;          // 0..7  (y quad)
    const int hbase = (2 * qy) * HX + (2 * qx + 2);  // halo idx of pixel (2qy,2qx); even
    const int eb = hbase >> 1;

    const float* erb  = er  + (size_t)b * NC * HW;
    const int*   segb = seg + b * HW;
    const int*   gtbb = gtb + b * HW;

    // --- stage labels once per tile ---
    for (int pix = tid; pix < NPIX; pix += NT) {
        int ly = pix / HX, lx = pix - ly * HX;
        int gh = h0 + ly, gw = w0 - 2 + lx;
        int code = 255;
        if (gh < NH && gw >= 0 && gw < NW) {
            int s = segb[gh * NW + gw];
            int g = gtbb[gh * NW + gw];
            int s0 = (s == 255) ? 0 : s;
            int g0 = (g == 255) ? 0 : g;
            bool fg    = (s0 * g0 > 0);
            bool inter = (gh >= 2 && gh < NH - 2 && gw >= 2 && gw < NW - 2);
            code = (s & 0xFFFF) | ((fg && inter) ? 0x10000 : 0) | (fg ? 0x20000 : 0);
        }
        shLab[pix] = code;
    }

    float d0[12], d1[12], d2[12], d3[12];
#pragma unroll
    for (int k = 0; k < 12; k++) { d0[k] = 0.f; d1[k] = 0.f; d2[k] = 0.f; d3[k] = 0.f; }
    float selfAcc[6] = {0.f, 0.f, 0.f, 0.f, 0.f, 0.f};

    for (int cg = 0; cg < NCHUNK; cg++) {
        // --- stage: each thread packs 4 channels of one pixel -> one STS.128 ---
#pragma unroll
        for (int q = 0; q < 4; q++) {
            const float* src = erb + (size_t)(cg * CC + q * 4) * HW;
            for (int pix = tid; pix < NPIX; pix += NT) {
                int ly = pix / HX, lx = pix - ly * HX;
                int gh = h0 + ly, gw = w0 - 2 + lx;
                float4 v = make_float4(0.f, 0.f, 0.f, 0.f);
                if (gh < NH && gw >= 0 && gw < NW) {
                    int off = gh * NW + gw;
                    v.x = src[off];
                    v.y = src[off + HW];
                    v.z = src[off + 2 * HW];
                    v.w = src[off + 3 * HW];
                }
                sh[q * NPIX + (pix >> 1) + (pix & 1) * HALF] = v;
            }
        }
        __syncthreads();

        // --- compute: 22 loads per quad serve 48 shift-dots (4 px x 12) ---
#pragma unroll
        for (int q = 0; q < 4; q++) {
            const float4* row = sh + q * NPIX;
#define AT(k) row[eb + ((k) >> 1) + (((k) & 1) * HALF)]
            float4 s00 = AT(0), s01 = AT(1), s10 = AT(36), s11 = AT(37);
            {   // row 0 (dy=0)
                float4 n2 = AT(2), n3 = AT(3);
                d0[0] += dot4(s00, s01); d0[1] += dot4(s00, n2);
                d1[0] += dot4(s01, n2);  d1[1] += dot4(s01, n3);
            }
            {   // row 1 (k = 34..39)
                float4 m0 = AT(34), m1 = AT(35), m4 = AT(38), m5 = AT(39);
                d0[2] += dot4(s00, m0); d0[3] += dot4(s00, m1); d0[4] += dot4(s00, s10);
                d0[5] += dot4(s00, s11); d0[6] += dot4(s00, m4);
                d1[2] += dot4(s01, m1); d1[3] += dot4(s01, s10); d1[4] += dot4(s01, s11);
                d1[5] += dot4(s01, m4); d1[6] += dot4(s01, m5);
                d2[0] += dot4(s10, s11); d2[1] += dot4(s10, m4);
                d3[0] += dot4(s11, m4);  d3[1] += dot4(s11, m5);
            }
            {   // row 2 (k = 70..75)
                float4 m0 = AT(70), m1 = AT(71), m2 = AT(72), m3 = AT(73), m4 = AT(74), m5 = AT(75);
                d0[7] += dot4(s00, m0); d0[8] += dot4(s00, m1); d0[9] += dot4(s00, m2);
                d0[10] += dot4(s00, m3); d0[11] += dot4(s00, m4);
                d1[7] += dot4(s01, m1); d1[8] += dot4(s01, m2); d1[9] += dot4(s01, m3);
                d1[10] += dot4(s01, m4); d1[11] += dot4(s01, m5);
                d2[2] += dot4(s10, m0); d2[3] += dot4(s10, m1); d2[4] += dot4(s10, m2);
                d2[5] += dot4(s10, m3); d2[6] += dot4(s10, m4);
                d3[2] += dot4(s11, m1); d3[3] += dot4(s11, m2); d3[4] += dot4(s11, m3);
                d3[5] += dot4(s11, m4); d3[6] += dot4(s11, m5);
            }
            {   // row 3 (k = 106..111)
                float4 m0 = AT(106), m1 = AT(107), m2 = AT(108), m3 = AT(109), m4 = AT(110), m5 = AT(111);
                d2[7] += dot4(s10, m0); d2[8] += dot4(s10, m1); d2[9] += dot4(s10, m2);
                d2[10] += dot4(s10, m3); d2[11] += dot4(s10, m4);
                d3[7] += dot4(s11, m1); d3[8] += dot4(s11, m2); d3[9] += dot4(s11, m3);
                d3[10] += dot4(s11, m4); d3[11] += dot4(s11, m5);
            }
#undef AT
            // distributed self-dots (for all 648 halo norms)
#pragma unroll
            for (int kk = 0; kk < 5; kk++) {
                int pix = tid + kk * NT;
                float4 a = row[(pix >> 1) + (pix & 1) * HALF];
                selfAcc[kk] += dot4(a, a);
            }
            if (tid < NPIX - 5 * NT) {   // tid < 8
                int pix = tid + 5 * NT;
                float4 a = row[(pix >> 1) + (pix & 1) * HALF];
                selfAcc[5] += dot4(a, a);
            }
        }
        __syncthreads();
    }

    // --- norms ---
#pragma unroll
    for (int kk = 0; kk < 5; kk++)
        shNorm[tid + kk * NT] = fmaxf(sqrtf(selfAcc[kk]), EPSF);
    if (tid < NPIX - 5 * NT)
        shNorm[tid + 5 * NT] = fmaxf(sqrtf(selfAcc[5]), EPSF);
    __syncthreads();

    // --- epilogue: 4 pixels per thread, branchless pair weights ---
    const int doffs[12] = {1, 2, 34, 35, 36, 37, 38, 70, 71, 72, 73, 74};
    float acc = 0.f;
    int cnt = 0, inc = 0;

#define EPI(DARR, PYO, PXO) {                                              \
        int mp = (2 * qy + (PYO)) * HX + (2 * qx + (PXO)) + 2;             \
        int pcode = shLab[mp];                                             \
        float vp = (float)((pcode >> 16) & 1);                             \
        cnt += (pcode >> 16) & 1;                                          \
        inc |= (pcode >> 17) & 1;                                          \
        int sp = pcode & 0xFFFF;                                           \
        float np = shNorm[mp];                                             \
        _Pragma("unroll")                                                  \
        for (int dd = 0; dd < 12; dd++) {                                  \
            int ncode = shLab[mp + doffs[dd]];                             \
            float vn = (float)((ncode >> 16) & 1);                         \
            float wgt = vp + vn;                                           \
            float nn = shNorm[mp + doffs[dd]];                             \
            float cosv = DARR[dd] / (np * nn);                             \
            int sn = ncode & 0xFFFF;                                       \
            float lab = (sp == sn && sp < 2) ? 1.f : 0.f;                  \
            float diff = cosv - lab;                                       \
            acc += wgt * diff * diff;                                      \
        }                                                                  \
    }
    EPI(d0, 0, 0);
    EPI(d1, 0, 1);
    EPI(d2, 1, 0);
    EPI(d3, 1, 1);
#undef EPI

    // --- block reduce (4 warps) + atomic merge per image ---
    unsigned mask = 0xFFFFFFFFu;
#pragma unroll
    for (int off = 16; off > 0; off >>= 1) {
        acc += __shfl_down_sync(mask, acc, off);
        cnt += __shfl_down_sync(mask, cnt, off);
        inc |= __shfl_down_sync(mask, inc, off);
    }
    if ((tid & 31) == 0) {
        shRedF[tid >> 5] = acc;
        shRedC[tid >> 5] = cnt;
        shRedI[tid >> 5] = inc;
    }
    __syncthreads();
    if (tid == 0) {
        float a = shRedF[0] + shRedF[1] + shRedF[2] + shRedF[3];
        int   c = shRedC[0] + shRedC[1] + shRedC[2] + shRedC[3];
        int   i = shRedI[0] | shRedI[1] | shRedI[2] | shRedI[3];
        atomicAdd(&g_total[b], a);
        if (c) atomicAdd(&g_cnt[b], c);
        if (i) atomicOr(&g_inc[b], 1);
    }
}

// ---------------------------------------------------------------------------
// Kernel 2: finalize scalar loss.
// ---------------------------------------------------------------------------
__global__ void final_kernel(float* __restrict__ out) {
    if (threadIdx.x == 0) {
        float sum = 0.f;
        int sn = 0;
        for (int b = 0; b < NB; b++) {
            sn += g_inc[b] ? 1 : 0;
            float cntf = fmaxf((float)g_cnt[b], 1.0f);
            float li = g_total[b] / cntf / 24.0f;
            if (g_inc[b]) sum += li;
        }
        int snn = (sn > 0) ? sn : 1;
        out[0] = sum / (float)snn;
    }
}

extern "C" void kernel_launch(void* const* d_in, const int* in_sizes, int n_in,
                              void* d_out, int out_size) {
    const float* er  = (const float*)d_in[0];
    const int*   seg = (const int*)d_in[1];
    const int*   gtb = (const int*)d_in[2];

    zero_kernel<<<1, 32>>>();
    dim3 grid(NW / TW, NH / TH, NB);   // 4 x 8 x 8 = 256 blocks
    context_kernel<<<grid, NT>>>(er, seg, gtb);
    final_kernel<<<1, 32>>>((float*)d_out);
}

// round 3
// speedup vs baseline: 2.7986x; 2.7986x over previous
#include <cuda_runtime.h>
#include <math.h>

// Problem constants
static constexpr int NB = 8, NC = 256, NH = 128, NW = 128;
static constexpr int HW = NH * NW;
static constexpr float EPSF = 1e-8f;

// Main-kernel tiling: core 16x32, halo 18x36 (half-shifts need dy>=0 only)
static constexpr int TH = 16, TW = 32;
static constexpr int HY = TH + 2, HX = TW + 4;   // 18 x 36
static constexpr int NPIX = HY * HX;             // 648
static constexpr int HALF = NPIX / 2;            // 324 even/odd swizzle split
static constexpr int NT = 128;                   // 2x2 pixel quad per thread
static constexpr int CSPLIT = 4;                 // channel groups (parallelism)
static constexpr int CPG = NC / CSPLIT;          // 64 channels per block
static constexpr int CC = 16;                    // channels staged per chunk
static constexpr int NCHUNK = CPG / CC;          // 4

// Epilogue strips
static constexpr int NSTRIP = 16;                // 8 rows each

// Device scratch (plain stores only; every element written each run)
__device__ float g_dots[CSPLIT][(size_t)NB * HW * 12];  // [(b*HW+p)*12 + d]
__device__ float g_nsq [CSPLIT][NB * HW];
__device__ float g_stotal[NB * NSTRIP];
__device__ int   g_scnt [NB * NSTRIP];
__device__ int   g_sinc [NB * NSTRIP];

__device__ __forceinline__ float dot4(const float4& a, const float4& b) {
    return fmaf(a.x, b.x, fmaf(a.y, b.y, fmaf(a.z, b.z, a.w * b.w)));
}

// ---------------------------------------------------------------------------
// Kernel 1: partial dots + partial norm^2 for a 64-channel slice of a tile.
// 1024 blocks, 128 threads, 2x2 pixels/thread, conflict-free SMEM.
// ---------------------------------------------------------------------------
__global__ __launch_bounds__(NT, 4) void partial_kernel(const float* __restrict__ er)
{
    __shared__ float4 sh[4 * NPIX];   // 41472 B, even/odd-swizzled per channel-quad

    const int b  = blockIdx.z >> 2;
    const int cs = blockIdx.z & 3;
    const int h0 = blockIdx.y * TH;
    const int w0 = blockIdx.x * TW;
    const int tid = threadIdx.x;
    const int qx = tid & 15;
    const int qy = tid >> 4;
    const int eb = ((2 * qy) * HX + (2 * qx + 2)) >> 1;   // even halo idx / 2

    const float* erb = er + ((size_t)b * NC + cs * CPG) * HW;

    // Precompute staging slots (fixed across chunks)
    int  goff[6], sidx[6];
    bool inb[6];
#pragma unroll
    for (int kk = 0; kk < 6; kk++) {
        int pix = tid + kk * NT;
        if (pix < NPIX) {
            int ly = pix / HX, lx = pix - ly * HX;
            int gh = h0 + ly, gw = w0 - 2 + lx;
            inb[kk]  = (gh < NH) && (gw >= 0) && (gw < NW);
            goff[kk] = gh * NW + gw;
            sidx[kk] = (pix >> 1) + (pix & 1) * HALF;
        } else { inb[kk] = false; goff[kk] = 0; sidx[kk] = 0; }
    }
    const bool has5 = (tid < NPIX - 5 * NT);   // only tid<8

    float d0[12], d1[12], d2[12], d3[12];
#pragma unroll
    for (int k = 0; k < 12; k++) { d0[k] = 0.f; d1[k] = 0.f; d2[k] = 0.f; d3[k] = 0.f; }
    float self0 = 0.f, self1 = 0.f, self2 = 0.f, self3 = 0.f;

    for (int ch = 0; ch < NCHUNK; ch++) {
        // --- stage CC=16 channels: pack 4 channels/pixel -> STS.128, no conflicts ---
#pragma unroll
        for (int q = 0; q < 4; q++) {
            const float* src = erb + (size_t)(ch * CC + q * 4) * HW;
#pragma unroll
            for (int kk = 0; kk < 5; kk++) {
                float4 v = make_float4(0.f, 0.f, 0.f, 0.f);
                if (inb[kk]) {
                    int o = goff[kk];
                    v.x = src[o]; v.y = src[o + HW]; v.z = src[o + 2 * HW]; v.w = src[o + 3 * HW];
                }
                sh[q * NPIX + sidx[kk]] = v;
            }
            if (has5) {
                float4 v = make_float4(0.f, 0.f, 0.f, 0.f);
                if (inb[5]) {
                    int o = goff[5];
                    v.x = src[o]; v.y = src[o + HW]; v.z = src[o + 2 * HW]; v.w = src[o + 3 * HW];
                }
                sh[q * NPIX + sidx[5]] = v;
            }
        }
        __syncthreads();

        // --- compute: 22 LDS.128 per quad serve 48 shift-dots + 4 self-dots ---
#pragma unroll
        for (int q = 0; q < 4; q++) {
            const float4* row = sh + q * NPIX;
#define AT(k) row[eb + ((k) >> 1) + (((k) & 1) * HALF)]
            float4 s00 = AT(0), s01 = AT(1), s10 = AT(36), s11 = AT(37);
            self0 += dot4(s00, s00); self1 += dot4(s01, s01);
            self2 += dot4(s10, s10); self3 += dot4(s11, s11);
            {   // row 0 (dy=0)
                float4 n2 = AT(2), n3 = AT(3);
                d0[0] += dot4(s00, s01); d0[1] += dot4(s00, n2);
                d1[0] += dot4(s01, n2);  d1[1] += dot4(s01, n3);
            }
            {   // row 1
                float4 m0 = AT(34), m1 = AT(35), m4 = AT(38), m5 = AT(39);
                d0[2] += dot4(s00, m0); d0[3] += dot4(s00, m1); d0[4] += dot4(s00, s10);
                d0[5] += dot4(s00, s11); d0[6] += dot4(s00, m4);
                d1[2] += dot4(s01, m1); d1[3] += dot4(s01, s10); d1[4] += dot4(s01, s11);
                d1[5] += dot4(s01, m4); d1[6] += dot4(s01, m5);
                d2[0] += dot4(s10, s11); d2[1] += dot4(s10, m4);
                d3[0] += dot4(s11, m4);  d3[1] += dot4(s11, m5);
            }
            {   // row 2
                float4 m0 = AT(70), m1 = AT(71), m2 = AT(72), m3 = AT(73), m4 = AT(74), m5 = AT(75);
                d0[7] += dot4(s00, m0); d0[8] += dot4(s00, m1); d0[9] += dot4(s00, m2);
                d0[10] += dot4(s00, m3); d0[11] += dot4(s00, m4);
                d1[7] += dot4(s01, m1); d1[8] += dot4(s01, m2); d1[9] += dot4(s01, m3);
                d1[10] += dot4(s01, m4); d1[11] += dot4(s01, m5);
                d2[2] += dot4(s10, m0); d2[3] += dot4(s10, m1); d2[4] += dot4(s10, m2);
                d2[5] += dot4(s10, m3); d2[6] += dot4(s10, m4);
                d3[2] += dot4(s11, m1); d3[3] += dot4(s11, m2); d3[4] += dot4(s11, m3);
                d3[5] += dot4(s11, m4); d3[6] += dot4(s11, m5);
            }
            {   // row 3
                float4 m0 = AT(106), m1 = AT(107), m2 = AT(108), m3 = AT(109), m4 = AT(110), m5 = AT(111);
                d2[7] += dot4(s10, m0); d2[8] += dot4(s10, m1); d2[9] += dot4(s10, m2);
                d2[10] += dot4(s10, m3); d2[11] += dot4(s10, m4);
                d3[7] += dot4(s11, m1); d3[8] += dot4(s11, m2); d3[9] += dot4(s11, m3);
                d3[10] += dot4(s11, m4); d3[11] += dot4(s11, m5);
            }
#undef AT
        }
        __syncthreads();
    }

    // --- dense writeback (no atomics; each element written exactly once) ---
    const int p00 = (h0 + 2 * qy) * NW + (w0 + 2 * qx);
    float* dbase = g_dots[cs] + (size_t)b * HW * 12;
#define ST12(P, D) {                                                       \
        float4* dst = (float4*)(dbase + (size_t)(P) * 12);                 \
        dst[0] = make_float4(D[0], D[1], D[2],  D[3]);                     \
        dst[1] = make_float4(D[4], D[5], D[6],  D[7]);                     \
        dst[2] = make_float4(D[8], D[9], D[10], D[11]);                    \
    }
    ST12(p00,          d0);
    ST12(p00 + 1,      d1);
    ST12(p00 + NW,     d2);
    ST12(p00 + NW + 1, d3);
#undef ST12
    float* nptr = g_nsq[cs] + b * HW;
    nptr[p00] = self0; nptr[p00 + 1] = self1;
    nptr[p00 + NW] = self2; nptr[p00 + NW + 1] = self3;
}

// ---------------------------------------------------------------------------
// Kernel 2: epilogue. One block per (8-row strip, image). 1024 threads.
// Sums the 4 channel slices, builds norms+labels in SMEM, accumulates loss.
// ---------------------------------------------------------------------------
__global__ __launch_bounds__(1024) void epilogue_kernel(
    const int* __restrict__ seg, const int* __restrict__ gtb)
{
    __shared__ float shN[12 * 132];
    __shared__ int   shL[12 * 132];
    __shared__ float sRf[32];
    __shared__ int   sRc[32], sRi[32];

    const int strip = blockIdx.x;
    const int b     = blockIdx.y;
    const int h0    = strip * 8;
    const int tid   = threadIdx.x;
    const int* segb = seg + b * HW;
    const int* gtbb = gtb + b * HW;

    // Stage norms + label codes for rows [h0-2, h0+10), cols [-2, 130)
    for (int i = tid; i < 12 * 132; i += 1024) {
        int r = i / 132, c = i - r * 132;
        int gh = h0 - 2 + r, gw = c - 2;
        float nrm = 1.f;
        int code = 0x7FFF;   // never matches a real label; flags 0
        if (gh >= 0 && gh < NH && gw >= 0 && gw < NW) {
            int idx = b * HW + gh * NW + gw;
            float ns = g_nsq[0][idx] + g_nsq[1][idx] + g_nsq[2][idx] + g_nsq[3][idx];
            nrm = fmaxf(sqrtf(ns), EPSF);
            int li = gh * NW + gw;
            int s = segb[li], g = gtbb[li];
            int s0 = (s == 255) ? 0 : s;
            int g0 = (g == 255) ? 0 : g;
            bool fg    = (s0 * g0 > 0);
            bool inter = (gh >= 2 && gh < NH - 2 && gw >= 2 && gw < NW - 2);
            code = (s & 0xFFFF) | ((fg && inter) ? 0x10000 : 0) | (fg ? 0x20000 : 0);
        }
        shN[i] = nrm;
        shL[i] = code;
    }
    __syncthreads();

    const int ty = tid >> 7, tx = tid & 127;
    const int p  = (h0 + ty) * NW + tx;

    // Sum the 4 slice dot-partials (3 float4 each)
    float dsum[12];
    {
        const size_t off = ((size_t)b * HW + p) * 12;
        float4 a0, a1, a2;
        {
            const float4* s = (const float4*)(g_dots[0] + off);
            a0 = s[0]; a1 = s[1]; a2 = s[2];
        }
#pragma unroll
        for (int cs = 1; cs < CSPLIT; cs++) {
            const float4* s = (const float4*)(g_dots[cs] + off);
            float4 t0 = s[0], t1 = s[1], t2 = s[2];
            a0.x += t0.x; a0.y += t0.y; a0.z += t0.z; a0.w += t0.w;
            a1.x += t1.x; a1.y += t1.y; a1.z += t1.z; a1.w += t1.w;
            a2.x += t2.x; a2.y += t2.y; a2.z += t2.z; a2.w += t2.w;
        }
        dsum[0] = a0.x; dsum[1] = a0.y; dsum[2]  = a0.z; dsum[3]  = a0.w;
        dsum[4] = a1.x; dsum[5] = a1.y; dsum[6]  = a1.z; dsum[7]  = a1.w;
        dsum[8] = a2.x; dsum[9] = a2.y; dsum[10] = a2.z; dsum[11] = a2.w;
    }

    const int mp = (ty + 2) * 132 + (tx + 2);
    const int dof[12] = {1, 2,
                         132 - 2, 132 - 1, 132, 132 + 1, 132 + 2,
                         264 - 2, 264 - 1, 264, 264 + 1, 264 + 2};

    int pcode = shL[mp];
    float vp  = (float)((pcode >> 16) & 1);
    int   cnt = (pcode >> 16) & 1;
    int   inc = (pcode >> 17) & 1;
    int   sp  = pcode & 0xFFFF;
    float np  = shN[mp];

    float acc = 0.f;
#pragma unroll
    for (int d = 0; d < 12; d++) {
        int ncode = shL[mp + dof[d]];
        float vn  = (float)((ncode >> 16) & 1);
        float wgt = vp + vn;
        float nn  = shN[mp + dof[d]];
        float cosv = dsum[d] / (np * nn);
        int sn = ncode & 0xFFFF;
        float lab = (sp == sn && sp < 2) ? 1.f : 0.f;
        float diff = cosv - lab;
        acc += wgt * diff * diff;
    }

    // Block reduce (32 warps)
    unsigned mask = 0xFFFFFFFFu;
#pragma unroll
    for (int off = 16; off > 0; off >>= 1) {
        acc += __shfl_down_sync(mask, acc, off);
        cnt += __shfl_down_sync(mask, cnt, off);
        inc |= __shfl_down_sync(mask, inc, off);
    }
    if ((tid & 31) == 0) { sRf[tid >> 5] = acc; sRc[tid >> 5] = cnt; sRi[tid >> 5] = inc; }
    __syncthreads();
    if (tid < 32) {
        float a = sRf[tid]; int c = sRc[tid]; int i = sRi[tid];
#pragma unroll
        for (int off = 16; off > 0; off >>= 1) {
            a += __shfl_down_sync(mask, a, off);
            c += __shfl_down_sync(mask, c, off);
            i |= __shfl_down_sync(mask, i, off);
        }
        if (tid == 0) {
            g_stotal[b * NSTRIP + strip] = a;
            g_scnt [b * NSTRIP + strip] = c;
            g_sinc [b * NSTRIP + strip] = i;
        }
    }
}

// ---------------------------------------------------------------------------
// Kernel 3: finalize scalar loss.
// ---------------------------------------------------------------------------
__global__ void final_kernel(float* __restrict__ out) {
    __shared__ float sLi[NB];
    __shared__ int   sIn[NB];
    int t = threadIdx.x;
    if (t < NB) {
        float tot = 0.f; int cnt = 0, inc = 0;
        for (int s = 0; s < NSTRIP; s++) {
            tot += g_stotal[t * NSTRIP + s];
            cnt += g_scnt [t * NSTRIP + s];
            inc |= g_sinc [t * NSTRIP + s];
        }
        sLi[t] = inc ? (tot / fmaxf((float)cnt, 1.f) / 24.f) : 0.f;
        sIn[t] = inc ? 1 : 0;
    }
    __syncthreads();
    if (t == 0) {
        float sum = 0.f; int sn = 0;
        for (int bb = 0; bb < NB; bb++) { sum += sLi[bb]; sn += sIn[bb]; }
        out[0] = sum / (float)(sn > 0 ? sn : 1);
    }
}

extern "C" void kernel_launch(void* const* d_in, const int* in_sizes, int n_in,
                              void* d_out, int out_size) {
    const float* er  = (const float*)d_in[0];
    const int*   seg = (const int*)d_in[1];
    const int*   gtb = (const int*)d_in[2];

    dim3 gridP(NW / TW, NH / TH, NB * CSPLIT);   // 4 x 8 x 32 = 1024 blocks
    partial_kernel<<<gridP, NT>>>(er);
    dim3 gridE(NSTRIP, NB);                      // 16 x 8 = 128 blocks
    epilogue_kernel<<<gridE, 1024>>>(seg, gtb);
    final_kernel<<<1, 32>>>((float*)d_out);
}